// round 1
// baseline (speedup 1.0000x reference)
#include <cuda_runtime.h>

#define D 64
#define KC 512
#define ROWSB 128
#define NTHR 256
#define XS_STRIDE 132
#define WS_STRIDE 516

__device__ float g_csqr[KC];

// Replicate reference: square (rounded) then sequential sum — no FMA contraction.
__global__ void csqr_kernel(const float* __restrict__ cbk) {
    int c = threadIdx.x;
    if (c < KC) {
        float s = 0.0f;
        #pragma unroll
        for (int k = 0; k < D; ++k) {
            float v = cbk[c * D + k];
            s = __fadd_rn(s, __fmul_rn(v, v));
        }
        g_csqr[c] = s;
    }
}

__device__ __forceinline__ unsigned long long pack2(float lo, float hi) {
    unsigned long long r;
    asm("mov.b64 %0, {%1, %2};" : "=l"(r) : "f"(lo), "f"(hi));
    return r;
}
__device__ __forceinline__ void unpack2(unsigned long long v, float& lo, float& hi) {
    asm("mov.b64 {%0, %1}, %2;" : "=f"(lo), "=f"(hi) : "l"(v));
}
__device__ __forceinline__ void fma2(unsigned long long& acc, unsigned long long a,
                                     unsigned long long b) {
    asm("fma.rn.f32x2 %0, %1, %2, %0;" : "+l"(acc) : "l"(a), "l"(b));
}

extern __shared__ float smem_f[];

__global__ void __launch_bounds__(NTHR, 1)
vq_kernel(const float* __restrict__ x, const float* __restrict__ cbk,
          float* __restrict__ out, int n) {
    float* Ws   = smem_f;                        // [64][516] codebook^T
    float* Xs   = Ws + D * WS_STRIDE;            // [64][132] x tile^T
    float* Cs   = Xs + D * XS_STRIDE;            // [512] c_sqr
    float* redv = Cs + KC;                       // [128][16]
    int*   redi = (int*)(redv + ROWSB * 16);     // [128][16]
    int*   sidx = redi + ROWSB * 16;             // [128]

    const int tid = threadIdx.x;
    const int rowbase = blockIdx.x * ROWSB;

    // Load codebook [512][64] -> Ws transposed [k][code]
    for (int e4 = tid; e4 < KC * D / 4; e4 += NTHR) {
        int e = e4 * 4;
        int code = e >> 6;
        int k = e & 63;
        float4 v = ((const float4*)cbk)[e4];
        Ws[(k + 0) * WS_STRIDE + code] = v.x;
        Ws[(k + 1) * WS_STRIDE + code] = v.y;
        Ws[(k + 2) * WS_STRIDE + code] = v.z;
        Ws[(k + 3) * WS_STRIDE + code] = v.w;
    }
    // Load x tile [128][64] -> Xs transposed [k][row]
    for (int e4 = tid; e4 < ROWSB * D / 4; e4 += NTHR) {
        int e = e4 * 4;
        int r = e >> 6;
        int k = e & 63;
        int gr = rowbase + r;
        float4 v = make_float4(0.f, 0.f, 0.f, 0.f);
        if (gr < n) v = ((const float4*)x)[(size_t)gr * (D / 4) + (k >> 2)];
        Xs[(k + 0) * XS_STRIDE + r] = v.x;
        Xs[(k + 1) * XS_STRIDE + r] = v.y;
        Xs[(k + 2) * XS_STRIDE + r] = v.z;
        Xs[(k + 3) * XS_STRIDE + r] = v.w;
    }
    for (int c = tid; c < KC; c += NTHR) Cs[c] = g_csqr[c];
    __syncthreads();

    const int rowT = tid & 15;
    const int codeT = tid >> 4;
    const int r0 = rowT * 8;   // 8 rows per thread
    const int c0 = codeT * 32; // 32 codes per thread

    // x_sqr per row: square (rounded) then sequential sum, like the reference.
    float xsq[8];
    #pragma unroll
    for (int rr = 0; rr < 8; ++rr) {
        float s = 0.0f;
        for (int k = 0; k < D; ++k) {
            float v = Xs[k * XS_STRIDE + r0 + rr];
            s = __fadd_rn(s, __fmul_rn(v, v));
        }
        xsq[rr] = s;
    }

    float bestv[8];
    int besti[8];
    #pragma unroll
    for (int rr = 0; rr < 8; ++rr) { bestv[rr] = 3.4e38f; besti[rr] = 0; }

    // Stream codes in chunks of 8; 8 rows x 8 codes register tile, f32x2-packed rows.
    for (int chunk = 0; chunk < 4; ++chunk) {
        const int cb0 = c0 + chunk * 8;
        unsigned long long acc[4][8];
        #pragma unroll
        for (int rp = 0; rp < 4; ++rp)
            #pragma unroll
            for (int cc = 0; cc < 8; ++cc) acc[rp][cc] = 0ULL;

        #pragma unroll 4
        for (int k = 0; k < D; ++k) {
            const float* xrow = Xs + k * XS_STRIDE + r0;
            unsigned long long x2[4];
            #pragma unroll
            for (int rp = 0; rp < 4; ++rp)
                x2[rp] = *(const unsigned long long*)(xrow + rp * 2);
            const float* wrow = Ws + k * WS_STRIDE + cb0;
            float4 wa = *(const float4*)(wrow);
            float4 wb = *(const float4*)(wrow + 4);
            float w[8] = {wa.x, wa.y, wa.z, wa.w, wb.x, wb.y, wb.z, wb.w};
            #pragma unroll
            for (int cc = 0; cc < 8; ++cc) {
                unsigned long long w2 = pack2(w[cc], w[cc]);
                #pragma unroll
                for (int rp = 0; rp < 4; ++rp) fma2(acc[rp][cc], x2[rp], w2);
            }
        }

        // Fold into running argmin. dist = fl(fl(xsq + csq) - 2*dot) — FFMA(-2,dot,t)
        // gives the single final rounding (2*dot is exact), matching the reference.
        #pragma unroll
        for (int cc = 0; cc < 8; ++cc) {
            const int code = cb0 + cc;
            const float cs = Cs[code];
            #pragma unroll
            for (int rp = 0; rp < 4; ++rp) {
                float d0, d1;
                unpack2(acc[rp][cc], d0, d1);
                float t0 = __fadd_rn(xsq[rp * 2 + 0], cs);
                float t1 = __fadd_rn(xsq[rp * 2 + 1], cs);
                float dist0 = __fmaf_rn(-2.0f, d0, t0);
                float dist1 = __fmaf_rn(-2.0f, d1, t1);
                if (dist0 < bestv[rp * 2 + 0]) { bestv[rp * 2 + 0] = dist0; besti[rp * 2 + 0] = code; }
                if (dist1 < bestv[rp * 2 + 1]) { bestv[rp * 2 + 1] = dist1; besti[rp * 2 + 1] = code; }
            }
        }
    }

    #pragma unroll
    for (int rr = 0; rr < 8; ++rr) {
        redv[(r0 + rr) * 16 + codeT] = bestv[rr];
        redi[(r0 + rr) * 16 + codeT] = besti[rr];
    }
    __syncthreads();

    const size_t nD = (size_t)n * D;
    if (tid < ROWSB) {
        int row = tid;
        float bv = redv[row * 16 + 0];
        int bi = redi[row * 16 + 0];
        // Ascending codeT scan + strict < == lowest-index tie-break (jnp.argmin).
        #pragma unroll
        for (int ct = 1; ct < 16; ++ct) {
            float v = redv[row * 16 + ct];
            int i2 = redi[row * 16 + ct];
            if (v < bv) { bv = v; bi = i2; }
        }
        sidx[row] = bi;
        int gr = rowbase + row;
        if (gr < n) out[2 * nD + gr] = (float)bi;  // indices (as output dtype)
    }
    __syncthreads();

    // Gather codebook[idx] into both z_q_x and z_q_x_bar.
    for (int i = tid; i < ROWSB * (D / 4); i += NTHR) {
        int row = i >> 4;
        int q = i & 15;
        int gr = rowbase + row;
        if (gr < n) {
            float4 v = ((const float4*)cbk)[sidx[row] * (D / 4) + q];
            ((float4*)(out + (size_t)gr * D))[q] = v;
            ((float4*)(out + nD + (size_t)gr * D))[q] = v;
        }
    }
}

extern "C" void kernel_launch(void* const* d_in, const int* in_sizes, int n_in,
                              void* d_out, int out_size) {
    const float* x = (const float*)d_in[0];
    const float* cbk = (const float*)d_in[1];
    float* out = (float*)d_out;
    const int n = in_sizes[0] / D;

    size_t smem = (size_t)(D * WS_STRIDE + D * XS_STRIDE + KC + ROWSB * 16) * sizeof(float)
                + (size_t)(ROWSB * 16 + ROWSB) * sizeof(int);
    cudaFuncSetAttribute(vq_kernel, cudaFuncAttributeMaxDynamicSharedMemorySize, (int)smem);

    csqr_kernel<<<1, KC>>>(cbk);
    int grid = (n + ROWSB - 1) / ROWSB;
    vq_kernel<<<grid, NTHR, smem>>>(x, cbk, out, n);
}